// round 7
// baseline (speedup 1.0000x reference)
#include <cuda_runtime.h>

#define BN 128
#define PN 24564
#define ON 20
#define CHUNKS 3
#define CHUNK (PN / CHUNKS)        // 8188 (exact: 3*8188 = 24564)
#define HALF (CHUNK / 2)           // 4094
#define NQ (PN / 4)                // 6141 quads per image
#define THRESH 0.5f

// ---- scratch (static device globals; no runtime allocation) ----
__device__ unsigned long long g_bestprior[BN * ON];  // packed (iou_bits<<32)|(~p)
__device__ unsigned char     g_match[BN * PN];       // (best_truth_idx<<1) | pos
__device__ int               g_npos;
__device__ double            g_acc[2];               // loss_l, loss_c

// ---------------------------------------------------------------- init (3 slots so k_match is launch #4 for ncu)
__global__ void k_init_a() {
    int i = blockIdx.x * blockDim.x + threadIdx.x;
    if (i < BN * ON) g_bestprior[i] = 0ULL;
}
__global__ void k_init_b() {
    if (threadIdx.x == 0) { g_npos = 0; g_acc[0] = 0.0; g_acc[1] = 0.0; }
}
__global__ void k_init_c() { }

// ---------------------------------------------------------------- matching
__global__ __launch_bounds__(256, 3)
void k_match(const float4* __restrict__ priors, const float* __restrict__ gt) {
    __shared__ float4 sbox[ON];
    __shared__ float  sarea[ON];
    __shared__ unsigned long long red[ON][8];

    const int b    = blockIdx.y;
    const int tid  = threadIdx.x;
    const int lane = tid & 31;
    const int wid  = tid >> 5;

    if (tid < ON) {
        const float* g = gt + (b * ON + tid) * 5;
        float4 v = make_float4(g[0], g[1], g[2], g[3]);
        sbox[tid]  = v;
        sarea[tid] = (v.z - v.x) * (v.w - v.y);
    }
    __syncthreads();

    float bo[ON];   // best iou per GT (this thread); 0 => untouched (argmax of zeros = 0)
    int   bp[ON];
#pragma unroll
    for (int o = 0; o < ON; o++) { bo[o] = 0.0f; bp[o] = 0; }

    const int p0 = blockIdx.x * CHUNK;

    for (int i = tid; i < HALF; i += 256) {
        const int pA = p0 + i;
        const int pB = pA + HALF;          // pA < pB always
        float4 prA = __ldg(&priors[pA]);
        float4 prB = __ldg(&priors[pB]);

        float ax0 = prA.x - prA.z * 0.5f, ay0 = prA.y - prA.w * 0.5f;
        float ax1 = prA.x + prA.z * 0.5f, ay1 = prA.y + prA.w * 0.5f;
        float aA  = (ax1 - ax0) * (ay1 - ay0);
        float bx0 = prB.x - prB.z * 0.5f, by0 = prB.y - prB.w * 0.5f;
        float bx1 = prB.x + prB.z * 0.5f, by1 = prB.y + prB.w * 0.5f;
        float aB  = (bx1 - bx0) * (by1 - by0);

        float mvA = 0.0f, mvB = 0.0f;
        int   moA = 0,    moB = 0;
#pragma unroll
        for (int o = 0; o < ON; o++) {
            float4 t  = sbox[o];
            float  sa = sarea[o];

            float wA = fminf(t.z, ax1) - fmaxf(t.x, ax0);
            float hA = fminf(t.w, ay1) - fmaxf(t.y, ay0);
            wA = fmaxf(wA, 0.0f); hA = fmaxf(hA, 0.0f);
            float iA = wA * hA;
            float vA = __fdividef(iA, sa + aA - iA);

            float wB = fminf(t.z, bx1) - fmaxf(t.x, bx0);
            float hB = fminf(t.w, by1) - fmaxf(t.y, by0);
            wB = fmaxf(wB, 0.0f); hB = fmaxf(hB, 0.0f);
            float iB = wB * hB;
            float vB = __fdividef(iB, sa + aB - iB);

            // strict > : first-o wins (jnp.argmax)
            if (vA > mvA) { mvA = vA; moA = o; }
            if (vB > mvB) { mvB = vB; moB = o; }
            // per-o best over p: A before B keeps smallest p on ties
            if (vA > bo[o]) { bo[o] = vA; bp[o] = pA; }
            if (vB > bo[o]) { bo[o] = vB; bp[o] = pB; }
        }
        g_match[b * PN + pA] = (unsigned char)((moA << 1) | (mvA >= THRESH ? 1 : 0));
        g_match[b * PN + pB] = (unsigned char)((moB << 1) | (mvB >= THRESH ? 1 : 0));
    }

    // warp-exact (max iou, min p), then cross-warp in smem, one atomic per (block,o)
#pragma unroll
    for (int o = 0; o < ON; o++) {
        unsigned ib = __float_as_uint(bo[o]);              // iou >= 0 -> monotonic bits
        unsigned m  = __reduce_max_sync(0xFFFFFFFFu, ib);
        unsigned cp = (ib == m) ? (unsigned)bp[o] : 0xFFFFFFFFu;
        unsigned pm = __reduce_min_sync(0xFFFFFFFFu, cp);  // smallest p among ties
        if (lane == 0)
            red[o][wid] = ((unsigned long long)m << 32)
                        | (unsigned long long)(0xFFFFFFFFu - pm);
    }
    __syncthreads();
    if (tid < ON) {
        unsigned long long best = red[tid][0];
#pragma unroll
        for (int w = 1; w < 8; w++) {
            unsigned long long c = red[tid][w];
            if (c > best) best = c;
        }
        atomicMax(&g_bestprior[b * ON + tid], best);
    }
}

// ---------------------------------------------------------------- override
// one warp per image: parallel loads, lane-0 ordered stores => last-o-wins
__global__ void k_override() {
    int b = blockIdx.x, lane = threadIdx.x;
    unsigned p = 0;
    if (lane < ON)
        p = 0xFFFFFFFFu - (unsigned)(g_bestprior[b * ON + lane] & 0xFFFFFFFFull);
#pragma unroll
    for (int o = 0; o < ON; o++) {
        unsigned pv = __shfl_sync(0xFFFFFFFFu, p, o);
        if (lane == 0)
            g_match[b * PN + pv] = (unsigned char)((o << 1) | 1);
    }
}

// ---------------------------------------------------------------- focal (all priors)
__device__ __forceinline__ float focal1(float c0, float c1, int cls) {
    // pc = softmax(conf)[cls] = sigmoid(z_cls - z_other)
    float z  = c0 - c1;
    float s  = (cls == 1) ? -z : z;
    float e  = __expf(-s);
    float pc = __fdividef(1.0f, 1.0f + e);
    pc = fminf(fmaxf(pc, 1e-7f), 1.0f - 1e-7f);
    float om = 1.0f - pc;
    return 0.25f * (-__logf(pc)) * om * om;
}

__device__ __forceinline__ float focal_quad(const float4* conf4, const int* slab,
                                            int b, int q) {
    int ix = b * PN + q * 4;
    uchar4 code = *(const uchar4*)&g_match[ix];
    float4 ca = __ldg(&conf4[ix >> 1]);
    float4 cb = __ldg(&conf4[(ix >> 1) + 1]);
    int c0 = (code.x & 1) ? slab[code.x >> 1] + 1 : 0;
    int c1 = (code.y & 1) ? slab[code.y >> 1] + 1 : 0;
    int c2 = (code.z & 1) ? slab[code.z >> 1] + 1 : 0;
    int c3 = (code.w & 1) ? slab[code.w >> 1] + 1 : 0;
    return focal1(ca.x, ca.y, c0) + focal1(ca.z, ca.w, c1)
         + focal1(cb.x, cb.y, c2) + focal1(cb.z, cb.w, c3);
}

__global__ __launch_bounds__(256)
void k_focal(const float4* __restrict__ conf4, const float* __restrict__ gt) {
    __shared__ int   slab[ON];
    __shared__ float swc[8];

    const int b   = blockIdx.y;
    const int tid = threadIdx.x;
    if (tid < ON) slab[tid] = (int)gt[(b * ON + tid) * 5 + 4];
    __syncthreads();

    float sc = 0.0f;
    int q0 = (blockIdx.x * 256 + tid) * 2;       // 2 quads = 8 priors per thread
    if (q0 < NQ)     sc  = focal_quad(conf4, slab, b, q0);
    if (q0 + 1 < NQ) sc += focal_quad(conf4, slab, b, q0 + 1);

#pragma unroll
    for (int off = 16; off; off >>= 1) sc += __shfl_down_sync(0xFFFFFFFFu, sc, off);
    if ((tid & 31) == 0) swc[tid >> 5] = sc;
    __syncthreads();
    if (tid == 0) {
        float t = 0.0f;
#pragma unroll
        for (int w = 0; w < 8; w++) t += swc[w];
        atomicAdd(&g_acc[1], (double)t);
    }
}

// ---------------------------------------------------------------- smooth-L1 over positives (scan g_match)
__device__ __forceinline__ float smooth_l1(float d) {
    float ad = fabsf(d);
    return (ad < 1.0f) ? 0.5f * d * d : ad - 0.5f;
}

__global__ __launch_bounds__(256)
void k_pos(const float4* __restrict__ loc, const float4* __restrict__ priors,
           const float* __restrict__ gt) {
    __shared__ float4 sbox[ON];
    __shared__ float  swl[8];
    __shared__ int    swn[8];

    const int b   = blockIdx.y;
    const int tid = threadIdx.x;
    if (tid < ON) {
        const float* g = gt + (b * ON + tid) * 5;
        sbox[tid] = make_float4(g[0], g[1], g[2], g[3]);
    }
    __syncthreads();

    float sl = 0.0f; int cnt = 0;
    int q0 = (blockIdx.x * 256 + tid) * 2;
#pragma unroll
    for (int k = 0; k < 2; k++) {
        int q = q0 + k;
        if (q >= NQ) break;
        int p = q * 4;
        int ix = b * PN + p;
        uchar4 code = *(const uchar4*)&g_match[ix];
        unsigned cw = *(const unsigned*)&code;
        if (cw & 0x01010101u) {
            unsigned char cc[4] = {code.x, code.y, code.z, code.w};
#pragma unroll
            for (int j = 0; j < 4; j++) {
                if (cc[j] & 1) {
                    cnt++;
                    float4 mb = sbox[cc[j] >> 1];
                    float4 pr = __ldg(&priors[p + j]);
                    float4 ld = __ldg(&loc[ix + j]);
                    float iw = __fdividef(1.0f, pr.z);
                    float ih = __fdividef(1.0f, pr.w);
                    float gx = ((mb.x + mb.z) * 0.5f - pr.x) * 10.0f * iw;
                    float gy = ((mb.y + mb.w) * 0.5f - pr.y) * 10.0f * ih;
                    float gw = __logf((mb.z - mb.x) * iw) * 5.0f;
                    float gh = __logf((mb.w - mb.y) * ih) * 5.0f;
                    sl += smooth_l1(ld.x - gx) + smooth_l1(ld.y - gy)
                        + smooth_l1(ld.z - gw) + smooth_l1(ld.w - gh);
                }
            }
        }
    }

#pragma unroll
    for (int off = 16; off; off >>= 1) {
        sl  += __shfl_down_sync(0xFFFFFFFFu, sl, off);
        cnt += __shfl_down_sync(0xFFFFFFFFu, cnt, off);
    }
    if ((tid & 31) == 0) { swl[tid >> 5] = sl; swn[tid >> 5] = cnt; }
    __syncthreads();
    if (tid == 0) {
        float t = 0.0f; int n = 0;
#pragma unroll
        for (int w = 0; w < 8; w++) { t += swl[w]; n += swn[w]; }
        atomicAdd(&g_acc[0], (double)t);
        atomicAdd(&g_npos, n);
    }
}

// ---------------------------------------------------------------- finalize
__global__ void k_final(float* out) {
    double np = (double)g_npos;
    if (np < 1.0) np = 1.0;
    out[0] = (float)(g_acc[0] / np);
    out[1] = (float)(g_acc[1] / np);
}

// ---------------------------------------------------------------- launch
extern "C" void kernel_launch(void* const* d_in, const int* in_sizes, int n_in,
                              void* d_out, int out_size) {
    const float4* loc    = (const float4*)d_in[0];  // [B,P,4] f32
    const float4* conf4  = (const float4*)d_in[1];  // [B,P,2] f32, read as float4 pairs
    const float4* priors = (const float4*)d_in[2];  // [P,4]   f32
    const float*  gt     = (const float*)d_in[3];   // [B,O,5] f32

    k_init_a<<<(BN * ON + 255) / 256, 256>>>();
    k_init_b<<<1, 32>>>();
    k_init_c<<<1, 32>>>();                 // filler: k_match = launch #4 (profiled slot)

    dim3 gm(CHUNKS, BN);                   // 384 blocks, one full wave at occ 3
    k_match<<<gm, 256>>>(priors, gt);

    k_override<<<BN, 32>>>();

    dim3 gf((NQ / 2 + 255) / 256, BN);     // 12 x 128, 8 priors/thread
    k_focal<<<gf, 256>>>(conf4, gt);

    dim3 gp((NQ / 2 + 255) / 256, BN);
    k_pos<<<gp, 256>>>(loc, priors, gt);

    k_final<<<1, 1>>>((float*)d_out);
}

// round 8
// speedup vs baseline: 1.0181x; 1.0181x over previous
#include <cuda_runtime.h>

#define BN 128
#define PN 24564
#define ON 20
#define NCH 12
#define CH 2048            // 12*2048 = 24576 >= PN (last chunk clamped)
#define NQ (PN / 4)        // 6141
#define HB 0x3F000000u     // bits of 0.5f

// ---- scratch (static device globals; no runtime allocation) ----
__device__ unsigned      g_blockbo[BN * NCH * ON]; // per-(b,chunk,o) max iou bits
__device__ unsigned      g_bestp[BN * ON];         // per-(b,o) best prior index
__device__ unsigned char g_match[BN * PN];         // (idx<<2) | override<<1 | pos
__device__ int           g_npos;
__device__ double        g_acc[2];                 // loss_l, loss_c

// ---- bit-deterministic IoU (shared by k_match / k_findp / k_idx) ----
// _rn intrinsics block FFMA contraction => identical SASS DAG in all kernels.
__device__ __forceinline__ void corners(float4 pr, float& x0, float& y0,
                                        float& x1, float& y1, float& ap) {
    float hx = __fmul_rn(pr.z, 0.5f), hy = __fmul_rn(pr.w, 0.5f);
    x0 = __fadd_rn(pr.x, -hx); y0 = __fadd_rn(pr.y, -hy);
    x1 = __fadd_rn(pr.x,  hx); y1 = __fadd_rn(pr.y,  hy);
    ap = __fmul_rn(__fadd_rn(x1, -x0), __fadd_rn(y1, -y0));
}
__device__ __forceinline__ unsigned iou_bits(float x0, float y0, float x1, float y1,
                                             float ap, float4 t, float sa) {
    float w = __fadd_rn(fminf(t.z, x1), -fmaxf(t.x, x0));
    float h = __fadd_rn(fminf(t.w, y1), -fmaxf(t.y, y0));
    w = fmaxf(w, 0.0f); h = fmaxf(h, 0.0f);
    float inter = __fmul_rn(w, h);
    float den   = __fadd_rn(__fadd_rn(sa, ap), -inter);
    float v     = __fdividef(inter, den);      // iou >= 0 -> bits monotonic
    return __float_as_uint(v);
}

// ---------------------------------------------------------------- init (fillers keep k_match in ncu slot 4)
__global__ void k_init_a() {
    if (threadIdx.x == 0) { g_npos = 0; g_acc[0] = 0.0; g_acc[1] = 0.0; }
}
__global__ void k_init_b() { }
__global__ void k_init_c() { }

// ---------------------------------------------------------------- matching (hot): max-only, no predicates
__global__ __launch_bounds__(256, 4)
void k_match(const float4* __restrict__ priors, const float* __restrict__ gt) {
    __shared__ float4   sbox[ON];
    __shared__ float    sarea[ON];
    __shared__ unsigned red[ON][8];

    const int b = blockIdx.y, cx = blockIdx.x, tid = threadIdx.x;
    if (tid < ON) {
        const float* g = gt + (b * ON + tid) * 5;
        float4 v = make_float4(g[0], g[1], g[2], g[3]);
        sbox[tid]  = v;
        sarea[tid] = __fmul_rn(__fadd_rn(v.z, -v.x), __fadd_rn(v.w, -v.y));
    }
    __syncthreads();

    unsigned bo[ON];
#pragma unroll
    for (int o = 0; o < ON; o++) bo[o] = 0u;

    const int p0 = cx * CH;
#pragma unroll 1
    for (int i = tid; i < CH / 2; i += 256) {
        int pA = p0 + i;
        int pB = pA + CH / 2;
        if (pB > PN - 1) pB = PN - 1;       // last chunk: harmless duplicate evals
        float4 prA = __ldg(&priors[pA]);
        float4 prB = __ldg(&priors[pB]);
        float ax0, ay0, ax1, ay1, aA; corners(prA, ax0, ay0, ax1, ay1, aA);
        float bx0, by0, bx1, by1, aB; corners(prB, bx0, by0, bx1, by1, aB);

        unsigned mvA = 0u, mvB = 0u;
#pragma unroll
        for (int o = 0; o < ON; o++) {
            float4 t  = sbox[o];
            float  sa = sarea[o];
            unsigned vA = iou_bits(ax0, ay0, ax1, ay1, aA, t, sa);
            unsigned vB = iou_bits(bx0, by0, bx1, by1, aB, t, sa);
            mvA = max(mvA, vA);
            mvB = max(mvB, vB);
            bo[o] = max(bo[o], max(vA, vB));
        }
        g_match[b * PN + pA] = (unsigned char)(mvA >= HB);
        g_match[b * PN + pB] = (unsigned char)(mvB >= HB);
    }

    const int lane = tid & 31, wid = tid >> 5;
#pragma unroll
    for (int o = 0; o < ON; o++) {
        unsigned m = __reduce_max_sync(0xFFFFFFFFu, bo[o]);
        if (lane == 0) red[o][wid] = m;
    }
    __syncthreads();
    if (tid < ON) {
        unsigned m = red[tid][0];
#pragma unroll
        for (int w = 1; w < 8; w++) m = max(m, red[tid][w]);
        g_blockbo[(b * NCH + cx) * ON + tid] = m;
    }
}

// ---------------------------------------------------------------- find best prior per (b,o): rescan winning chunk
__global__ __launch_bounds__(256)
void k_findp(const float4* __restrict__ priors, const float* __restrict__ gt) {
    __shared__ unsigned sred[8];
    const int bo_ = blockIdx.x;
    const int b = bo_ / ON, o = bo_ % ON;
    const int tid = threadIdx.x;

    const float* g = gt + (b * ON + o) * 5;
    float4 t  = make_float4(g[0], g[1], g[2], g[3]);
    float  sa = __fmul_rn(__fadd_rn(t.z, -t.x), __fadd_rn(t.w, -t.y));

    unsigned M = 0u; int c = 0;
#pragma unroll
    for (int cc = NCH - 1; cc >= 0; cc--) {      // descending + >= : smallest chunk wins ties
        unsigned v = g_blockbo[(b * NCH + cc) * ON + o];
        if (v >= M) { M = v; c = cc; }
    }

    unsigned minp = 0x7FFFFFFFu;
    for (int i = tid; i < CH; i += 256) {
        int p = c * CH + i;
        if (p < PN) {
            float4 pr = __ldg(&priors[p]);
            float x0, y0, x1, y1, ap; corners(pr, x0, y0, x1, y1, ap);
            if (iou_bits(x0, y0, x1, y1, ap, t, sa) == M)
                minp = min(minp, (unsigned)p);
        }
    }
    minp = __reduce_min_sync(0xFFFFFFFFu, minp);
    if ((tid & 31) == 0) sred[tid >> 5] = minp;
    __syncthreads();
    if (tid == 0) {
        unsigned m = sred[0];
#pragma unroll
        for (int w = 1; w < 8; w++) m = min(m, sred[w]);
        if (m == 0x7FFFFFFFu) m = 0;             // safety (bit-exact => unreachable)
        g_bestp[b * ON + o] = m;
    }
}

// ---------------------------------------------------------------- override: serial per image => last-o-wins
__global__ void k_override() {
    int b = blockIdx.x, lane = threadIdx.x;
    unsigned p = (lane < ON) ? g_bestp[b * ON + lane] : 0u;
#pragma unroll
    for (int o = 0; o < ON; o++) {
        unsigned pv = __shfl_sync(0xFFFFFFFFu, p, o);
        if (lane == 0)
            g_match[b * PN + pv] = (unsigned char)((o << 2) | 3);
    }
}

// ---------------------------------------------------------------- recover idx for natural positives (sparse)
__global__ __launch_bounds__(256)
void k_idx(const float4* __restrict__ priors, const float* __restrict__ gt) {
    __shared__ float4 sbox[ON];
    __shared__ float  sarea[ON];
    const int b = blockIdx.y, tid = threadIdx.x;
    if (tid < ON) {
        const float* g = gt + (b * ON + tid) * 5;
        float4 v = make_float4(g[0], g[1], g[2], g[3]);
        sbox[tid]  = v;
        sarea[tid] = __fmul_rn(__fadd_rn(v.z, -v.x), __fadd_rn(v.w, -v.y));
    }
    __syncthreads();

    const int base = blockIdx.x * CH;
#pragma unroll 1
    for (int i = tid; i < CH; i += 256) {
        int p = base + i;
        if (p < PN && g_match[b * PN + p] == 1) {   // positive, not overridden
            float4 pr = __ldg(&priors[p]);
            float x0, y0, x1, y1, ap; corners(pr, x0, y0, x1, y1, ap);
            unsigned best = 0u; int mo = 0;
#pragma unroll
            for (int o = 0; o < ON; o++) {           // ascending + strict > : first-index argmax
                unsigned v = iou_bits(x0, y0, x1, y1, ap, sbox[o], sarea[o]);
                if (v > best) { best = v; mo = o; }
            }
            g_match[b * PN + p] = (unsigned char)((mo << 2) | 1);
        }
    }
}

// ---------------------------------------------------------------- focal over all priors
__device__ __forceinline__ float focal1(float c0, float c1, int cls) {
    float z  = c0 - c1;
    float s  = (cls == 1) ? -z : z;
    float e  = __expf(-s);
    float pc = __fdividef(1.0f, 1.0f + e);          // softmax[cls] via sigmoid
    pc = fminf(fmaxf(pc, 1e-7f), 1.0f - 1e-7f);
    float om = 1.0f - pc;
    return 0.25f * (-__logf(pc)) * om * om;
}
__device__ __forceinline__ float focal_quad(const float4* conf4, const int* slab,
                                            int b, int q) {
    int ix = b * PN + q * 4;
    uchar4 code = *(const uchar4*)&g_match[ix];
    float4 ca = __ldg(&conf4[ix >> 1]);
    float4 cb = __ldg(&conf4[(ix >> 1) + 1]);
    int c0 = (code.x & 1) ? slab[code.x >> 2] + 1 : 0;
    int c1 = (code.y & 1) ? slab[code.y >> 2] + 1 : 0;
    int c2 = (code.z & 1) ? slab[code.z >> 2] + 1 : 0;
    int c3 = (code.w & 1) ? slab[code.w >> 2] + 1 : 0;
    return focal1(ca.x, ca.y, c0) + focal1(ca.z, ca.w, c1)
         + focal1(cb.x, cb.y, c2) + focal1(cb.z, cb.w, c3);
}

__global__ __launch_bounds__(256)
void k_focal(const float4* __restrict__ conf4, const float* __restrict__ gt) {
    __shared__ int   slab[ON];
    __shared__ float swc[8];
    const int b = blockIdx.y, tid = threadIdx.x;
    if (tid < ON) slab[tid] = (int)gt[(b * ON + tid) * 5 + 4];
    __syncthreads();

    float sc = 0.0f;
#pragma unroll
    for (int k = 0; k < 4; k++) {                  // 16 priors/thread -> high MLP
        int q = blockIdx.x * 1024 + k * 256 + tid;
        if (q < NQ) sc += focal_quad(conf4, slab, b, q);
    }
#pragma unroll
    for (int off = 16; off; off >>= 1) sc += __shfl_down_sync(0xFFFFFFFFu, sc, off);
    if ((tid & 31) == 0) swc[tid >> 5] = sc;
    __syncthreads();
    if (tid == 0) {
        float t = 0.0f;
#pragma unroll
        for (int w = 0; w < 8; w++) t += swc[w];
        atomicAdd(&g_acc[1], (double)t);
    }
}

// ---------------------------------------------------------------- smooth-L1 over positives
__device__ __forceinline__ float smooth_l1(float d) {
    float ad = fabsf(d);
    return (ad < 1.0f) ? 0.5f * d * d : ad - 0.5f;
}

__global__ __launch_bounds__(256)
void k_pos(const float4* __restrict__ loc, const float4* __restrict__ priors,
           const float* __restrict__ gt) {
    __shared__ float4 sbox[ON];
    __shared__ float  swl[8];
    __shared__ int    swn[8];
    const int b = blockIdx.y, tid = threadIdx.x;
    if (tid < ON) {
        const float* g = gt + (b * ON + tid) * 5;
        sbox[tid] = make_float4(g[0], g[1], g[2], g[3]);
    }
    __syncthreads();

    float sl = 0.0f; int cnt = 0;
#pragma unroll
    for (int k = 0; k < 4; k++) {
        int q = blockIdx.x * 1024 + k * 256 + tid;
        if (q >= NQ) break;
        int p  = q * 4;
        int ix = b * PN + p;
        uchar4 code = *(const uchar4*)&g_match[ix];
        unsigned cw = *(const unsigned*)&code;
        if (cw & 0x01010101u) {
            unsigned char cc[4] = {code.x, code.y, code.z, code.w};
#pragma unroll
            for (int j = 0; j < 4; j++) {
                if (cc[j] & 1) {
                    cnt++;
                    float4 mb = sbox[cc[j] >> 2];
                    float4 pr = __ldg(&priors[p + j]);
                    float4 ld = __ldg(&loc[ix + j]);
                    float iw = __fdividef(1.0f, pr.z);
                    float ih = __fdividef(1.0f, pr.w);
                    float gx = ((mb.x + mb.z) * 0.5f - pr.x) * 10.0f * iw;
                    float gy = ((mb.y + mb.w) * 0.5f - pr.y) * 10.0f * ih;
                    float gw = __logf((mb.z - mb.x) * iw) * 5.0f;
                    float gh = __logf((mb.w - mb.y) * ih) * 5.0f;
                    sl += smooth_l1(ld.x - gx) + smooth_l1(ld.y - gy)
                        + smooth_l1(ld.z - gw) + smooth_l1(ld.w - gh);
                }
            }
        }
    }
#pragma unroll
    for (int off = 16; off; off >>= 1) {
        sl  += __shfl_down_sync(0xFFFFFFFFu, sl, off);
        cnt += __shfl_down_sync(0xFFFFFFFFu, cnt, off);
    }
    if ((tid & 31) == 0) { swl[tid >> 5] = sl; swn[tid >> 5] = cnt; }
    __syncthreads();
    if (tid == 0) {
        float t = 0.0f; int n = 0;
#pragma unroll
        for (int w = 0; w < 8; w++) { t += swl[w]; n += swn[w]; }
        atomicAdd(&g_acc[0], (double)t);
        atomicAdd(&g_npos, n);
    }
}

// ---------------------------------------------------------------- finalize
__global__ void k_final(float* out) {
    double np = (double)g_npos;
    if (np < 1.0) np = 1.0;
    out[0] = (float)(g_acc[0] / np);
    out[1] = (float)(g_acc[1] / np);
}

// ---------------------------------------------------------------- launch
extern "C" void kernel_launch(void* const* d_in, const int* in_sizes, int n_in,
                              void* d_out, int out_size) {
    const float4* loc    = (const float4*)d_in[0];  // [B,P,4] f32
    const float4* conf4  = (const float4*)d_in[1];  // [B,P,2] f32 as float4 pairs
    const float4* priors = (const float4*)d_in[2];  // [P,4]   f32
    const float*  gt     = (const float*)d_in[3];   // [B,O,5] f32

    k_init_a<<<1, 32>>>();
    k_init_b<<<1, 32>>>();
    k_init_c<<<1, 32>>>();                  // k_match = launch #4 (ncu slot)

    dim3 gm(NCH, BN);                       // 1536 blocks, occ 4/SM
    k_match<<<gm, 256>>>(priors, gt);

    k_findp<<<BN * ON, 256>>>(priors, gt);  // 2560 blocks

    k_override<<<BN, 32>>>();

    dim3 gi(NCH, BN);
    k_idx<<<gi, 256>>>(priors, gt);

    dim3 gf((NQ + 1023) / 1024, BN);        // 6 x 128
    k_focal<<<gf, 256>>>(conf4, gt);

    dim3 gp((NQ + 1023) / 1024, BN);
    k_pos<<<gp, 256>>>(loc, priors, gt);

    k_final<<<1, 1>>>((float*)d_out);
}